// round 11
// baseline (speedup 1.0000x reference)
#include <cuda_runtime.h>
#include <math.h>

// Problem constants
// x: (16, 256, 1024); first = x[:4], last = x[4:]
// tokens T = 4*1024 = 4096, hidden H = 1024
static constexpr int CC   = 256;
static constexpr int NN   = 1024;
static constexpr int NB   = 4;      // first batches
static constexpr int NZ   = 12;     // (group-1)*b attention pairs
static constexpr int TOK  = NB * NN;

// Scratch layout (floats)
static constexpr long OFF_XQ  = 0;                       // 12*256*1024
static constexpr long OFF_XK  = OFF_XQ  + 3145728;       // 4*256*1024
static constexpr long OFF_XVT = OFF_XK  + 1048576;       // 12*1024*256 (dup'd per z)
static constexpr long OFF_E   = OFF_XVT + 3145728;       // 12*1024*1024 (energy -> attn in place)
static constexpr long OFF_RT  = OFF_E   + 12582912;      // 4*1024*256
static constexpr long OFF_H   = OFF_RT  + 1048576;       // 4096*256
static constexpr long OFF_H1  = OFF_H   + 1048576;       // 4096*1024
static constexpr long OFF_H2  = OFF_H1  + 4194304;       // 4096*256
static constexpr long SCRATCH_TOTAL = OFF_H2 + 1048576;  // 27,262,976 floats (~109 MB)

__device__ float g_scratch[SCRATCH_TOTAL];

// ---------------------------------------------------------------------------
// Generic batched fp32 GEMM:  C[m][n] = alpha * sum_k opA[k][m] * opB[k][n]
//   AKM=true : A stored (K, M) row-major, lda = row stride (m contiguous)
//   AKM=false: A stored (M, K) row-major, lda = row stride (k contiguous) -> transpose on load
//   (same for B with N)
// Per-batch offsets: ptr + (mod ? (z % mod) : z) * stride
// Epilogue: optional per-col bias, optional residual (same layout as C), optional relu.
// Assumes M % BM == 0, N % BN == 0, K % BK == 0, all leading dims % 4 == 0.
// ---------------------------------------------------------------------------
template<int BM, int BN, int BK, int TM, int TN, bool AKM, bool BKM, int PA, int PB>
__global__ void __launch_bounds__((BM/TM)*(BN/TN))
gemm_k(const float* __restrict__ A, const float* __restrict__ B, float* __restrict__ C,
       int K, int lda, int ldb, int ldc,
       long asb, long bsb, long csb, int aMod, int bMod,
       float alpha, const float* __restrict__ bias,
       const float* __restrict__ res, int relu)
{
    constexpr int NT = (BM/TM)*(BN/TN);
    const int z = blockIdx.z;
    const float* Ab = A + (aMod ? (long)(z % aMod) * asb : (long)z * asb);
    const float* Bb = B + (bMod ? (long)(z % bMod) * bsb : (long)z * bsb);
    float* Cb = C + (long)z * csb;
    const float* Rb = res ? (res + (long)z * csb) : nullptr;

    const int bm = blockIdx.y * BM;
    const int bn = blockIdx.x * BN;

    __shared__ float As[BK][BM + PA];
    __shared__ float Bs[BK][BN + PB];

    const int tid = threadIdx.x;
    const int tx = tid % (BN / TN);
    const int ty = tid / (BN / TN);

    float acc[TM][TN];
#pragma unroll
    for (int i = 0; i < TM; i++)
#pragma unroll
        for (int j = 0; j < TN; j++) acc[i][j] = 0.f;

    for (int kt = 0; kt < K; kt += BK) {
        // ---- load A tile ----
        if (AKM) {
#pragma unroll
            for (int v = tid; v < BK * BM / 4; v += NT) {
                int kk = v / (BM / 4), mv = v % (BM / 4);
                float4 t = *(const float4*)(Ab + (long)(kt + kk) * lda + bm + mv * 4);
                *(float4*)&As[kk][mv * 4] = t;
            }
        } else {
#pragma unroll
            for (int v = tid; v < BK * BM / 4; v += NT) {
                int mm = v / (BK / 4), kv = v % (BK / 4);
                float4 t = *(const float4*)(Ab + (long)(bm + mm) * lda + kt + kv * 4);
                As[kv * 4 + 0][mm] = t.x;
                As[kv * 4 + 1][mm] = t.y;
                As[kv * 4 + 2][mm] = t.z;
                As[kv * 4 + 3][mm] = t.w;
            }
        }
        // ---- load B tile ----
        if (BKM) {
#pragma unroll
            for (int v = tid; v < BK * BN / 4; v += NT) {
                int kk = v / (BN / 4), nv = v % (BN / 4);
                float4 t = *(const float4*)(Bb + (long)(kt + kk) * ldb + bn + nv * 4);
                *(float4*)&Bs[kk][nv * 4] = t;
            }
        } else {
#pragma unroll
            for (int v = tid; v < BK * BN / 4; v += NT) {
                int nn = v / (BK / 4), kv = v % (BK / 4);
                float4 t = *(const float4*)(Bb + (long)(bn + nn) * ldb + kt + kv * 4);
                Bs[kv * 4 + 0][nn] = t.x;
                Bs[kv * 4 + 1][nn] = t.y;
                Bs[kv * 4 + 2][nn] = t.z;
                Bs[kv * 4 + 3][nn] = t.w;
            }
        }
        __syncthreads();

#pragma unroll
        for (int kk = 0; kk < BK; kk++) {
            float a[TM], bfr[TN];
            float4 a0 = *(const float4*)&As[kk][ty * TM];
            float4 a1 = *(const float4*)&As[kk][ty * TM + 4];
            a[0]=a0.x; a[1]=a0.y; a[2]=a0.z; a[3]=a0.w;
            a[4]=a1.x; a[5]=a1.y; a[6]=a1.z; a[7]=a1.w;
            float4 b0 = *(const float4*)&Bs[kk][tx * TN];
            float4 b1 = *(const float4*)&Bs[kk][tx * TN + 4];
            bfr[0]=b0.x; bfr[1]=b0.y; bfr[2]=b0.z; bfr[3]=b0.w;
            bfr[4]=b1.x; bfr[5]=b1.y; bfr[6]=b1.z; bfr[7]=b1.w;
#pragma unroll
            for (int i = 0; i < TM; i++)
#pragma unroll
                for (int j = 0; j < TN; j++)
                    acc[i][j] = fmaf(a[i], bfr[j], acc[i][j]);
        }
        __syncthreads();
    }

    // ---- epilogue ----
#pragma unroll
    for (int i = 0; i < TM; i++) {
        int cm = bm + ty * TM + i;
#pragma unroll
        for (int j = 0; j < TN; j++) {
            int cn = bn + tx * TN + j;
            float v = acc[i][j] * alpha;
            if (bias) v += bias[cn];
            if (Rb)   v += Rb[(long)cm * ldc + cn];
            if (relu) v = fmaxf(v, 0.f);
            Cb[(long)cm * ldc + cn] = v;
        }
    }
}

// ---------------------------------------------------------------------------
// In-place row softmax over the last dim of E[z][n][1024]
// ---------------------------------------------------------------------------
__global__ void softmax_inplace_k(float* __restrict__ E)
{
    const int n = blockIdx.x;
    const int z = blockIdx.y;
    float* row = E + ((long)z * NN + n) * NN;
    const int tid = threadIdx.x;  // 256

    float e[4];
#pragma unroll
    for (int k = 0; k < 4; k++) e[k] = row[tid + 256 * k];

    __shared__ float red[256];
    float m = fmaxf(fmaxf(e[0], e[1]), fmaxf(e[2], e[3]));
    red[tid] = m; __syncthreads();
    for (int s = 128; s > 0; s >>= 1) {
        if (tid < s) red[tid] = fmaxf(red[tid], red[tid + s]);
        __syncthreads();
    }
    m = red[0]; __syncthreads();

    float ssum = 0.f;
#pragma unroll
    for (int k = 0; k < 4; k++) { e[k] = expf(e[k] - m); ssum += e[k]; }
    red[tid] = ssum; __syncthreads();
    for (int s = 128; s > 0; s >>= 1) {
        if (tid < s) red[tid] += red[tid + s];
        __syncthreads();
    }
    float inv = 1.f / red[0];
#pragma unroll
    for (int k = 0; k < 4; k++) row[tid + 256 * k] = e[k] * inv;
}

// ---------------------------------------------------------------------------
// LN1: h[t][c] = LN_c( x[b][c][n] + Rt[t][c] ) * g + beta   (t = b*1024+n)
// ---------------------------------------------------------------------------
__global__ void ln1_k(const float* __restrict__ x, const float* __restrict__ Rt,
                      const float* __restrict__ gam, const float* __restrict__ bet,
                      float* __restrict__ h)
{
    const int t = blockIdx.x;
    const int b = t >> 10, n = t & 1023;
    const int c = threadIdx.x;
    float v = x[((long)b * CC + c) * NN + n] + Rt[(long)t * CC + c];

    __shared__ float red[256];
    red[c] = v; __syncthreads();
    for (int s = 128; s > 0; s >>= 1) { if (c < s) red[c] += red[c + s]; __syncthreads(); }
    float mu = red[0] * (1.f / CC); __syncthreads();
    float d = v - mu;
    red[c] = d * d; __syncthreads();
    for (int s = 128; s > 0; s >>= 1) { if (c < s) red[c] += red[c + s]; __syncthreads(); }
    float var = red[0] * (1.f / CC);
    float hv = d * rsqrtf(var + 1e-6f) * gam[c] + bet[c];
    h[(long)t * CC + c] = hv;
}

// ---------------------------------------------------------------------------
// LN2 + relu + transposed write to out[b][c][n] for b < 4
// ---------------------------------------------------------------------------
__global__ void ln2_out_k(const float* __restrict__ H2,
                          const float* __restrict__ gam, const float* __restrict__ bet,
                          float* __restrict__ out)
{
    const int t = blockIdx.x;
    const int b = t >> 10, n = t & 1023;
    const int c = threadIdx.x;
    float v = H2[(long)t * CC + c];

    __shared__ float red[256];
    red[c] = v; __syncthreads();
    for (int s = 128; s > 0; s >>= 1) { if (c < s) red[c] += red[c + s]; __syncthreads(); }
    float mu = red[0] * (1.f / CC); __syncthreads();
    float d = v - mu;
    red[c] = d * d; __syncthreads();
    for (int s = 128; s > 0; s >>= 1) { if (c < s) red[c] += red[c + s]; __syncthreads(); }
    float var = red[0] * (1.f / CC);
    float hv = d * rsqrtf(var + 1e-6f) * gam[c] + bet[c];
    out[((long)b * CC + c) * NN + n] = fmaxf(hv, 0.f);
}

// ---------------------------------------------------------------------------
extern "C" void kernel_launch(void* const* d_in, const int* in_sizes, int n_in,
                              void* d_out, int out_size)
{
    (void)in_sizes; (void)n_in; (void)out_size;
    const float* x     = (const float*)d_in[0];
    const float* Wq    = (const float*)d_in[1];
    const float* Wk    = (const float*)d_in[2];
    const float* Wv    = (const float*)d_in[3];
    const float* bv    = (const float*)d_in[4];
    const float* ln1_g = (const float*)d_in[5];
    const float* ln1_b = (const float*)d_in[6];
    const float* W1    = (const float*)d_in[7];
    const float* b1    = (const float*)d_in[8];
    const float* W2    = (const float*)d_in[9];
    const float* b2    = (const float*)d_in[10];
    const float* ln2_g = (const float*)d_in[11];
    const float* ln2_b = (const float*)d_in[12];
    float* out = (float*)d_out;

    float* S = nullptr;
    cudaGetSymbolAddress((void**)&S, g_scratch);
    float* xq  = S + OFF_XQ;
    float* xk  = S + OFF_XK;
    float* xvT = S + OFF_XVT;
    float* E   = S + OFF_E;
    float* Rt  = S + OFF_RT;
    float* h   = S + OFF_H;
    float* H1  = S + OFF_H1;
    float* H2  = S + OFF_H2;

    const float* xlast = x + (long)NB * CC * NN;

    // out[4:] = last (unchanged)
    cudaMemcpyAsync(out + (long)NB * CC * NN, xlast,
                    (size_t)12 * CC * NN * sizeof(float),
                    cudaMemcpyDeviceToDevice, 0);

    // xq[z=(B,s)][o][n] = Wq[s] @ last[B, s*64.., :]   48 batches of 64x1024x64
    gemm_k<64,128,16,8,8,false,true,4,0><<<dim3(8,1,48),128>>>(
        Wq, xlast, xq, 64, 64, NN, NN,
        (long)64*64, (long)64*NN, (long)64*NN, 4, 0,
        1.f, nullptr, nullptr, 0);

    // xk: 16 batches of 64x1024x64 over first
    gemm_k<64,128,16,8,8,false,true,4,0><<<dim3(8,1,16),128>>>(
        Wk, x, xk, 64, 64, NN, NN,
        (long)64*64, (long)64*NN, (long)64*NN, 4, 0,
        1.f, nullptr, nullptr, 0);

    // xvT[z][n][c] = (Wv @ x[z%4])^T + bv, duplicated per z (12 batches of 1024x256x256)
    gemm_k<128,128,16,8,8,true,false,0,4><<<dim3(2,8,12),256>>>(
        x, Wv, xvT, CC, NN, CC, CC,
        (long)CC*NN, 0L, (long)NN*CC, 4, 0,
        1.f, bv, nullptr, 0);

    // energy: E[z][n][m] = sum_ch xq[z][ch][n] * xk[z%4][ch][m]   12 x (1024x1024x256)
    gemm_k<128,128,16,8,8,true,true,0,0><<<dim3(8,8,12),256>>>(
        xq, xk, E, CC, NN, NN, NN,
        (long)CC*NN, (long)CC*NN, (long)NN*NN, 0, 4,
        1.f, nullptr, nullptr, 0);

    // softmax rows in place
    softmax_inplace_k<<<dim3(NN, NZ), 256>>>(E);

    // x_r mean (reshape trap!): per b', K = 3*1024 over contiguous z-blocks
    // Rt[b'][m][c] = (1/48) * sum_{k} attn_flat[3b'*1024 + k][m] * xvT_flat[3b'*1024 + k][c]
    gemm_k<128,128,16,8,8,true,true,0,0><<<dim3(2,8,NB),256>>>(
        E, xvT, Rt, 3*NN, NN, CC, CC,
        (long)3*NN*NN, (long)3*NN*CC, (long)NN*CC, 0, 0,
        1.f/48.f, nullptr, nullptr, 0);

    // LN1 (residual add inside)
    ln1_k<<<TOK, 256>>>(x, Rt, ln1_g, ln1_b, h);

    // MLP1: H1 = relu(h @ W1^T + b1)   4096x1024x256
    gemm_k<128,128,16,8,8,false,false,4,4><<<dim3(8,32,1),256>>>(
        h, W1, H1, CC, CC, CC, 4*CC,
        0L, 0L, 0L, 0, 0,
        1.f, b1, nullptr, 1);

    // MLP2: H2 = h + H1 @ W2^T + b2    4096x256x1024
    gemm_k<128,128,16,8,8,false,false,4,4><<<dim3(2,32,1),256>>>(
        H1, W2, H2, 4*CC, 4*CC, 4*CC, CC,
        0L, 0L, 0L, 0, 0,
        1.f, b2, h, 0);

    // LN2 + relu + transpose into out[:4]
    ln2_out_k<<<TOK, 256>>>(H2, ln2_g, ln2_b, out);
}

// round 12
// speedup vs baseline: 1.6066x; 1.6066x over previous
#include <cuda_runtime.h>
#include <math.h>
#include <stdint.h>

// Problem constants: x (16, 256, 1024); first = x[:4], last = x[4:]
static constexpr int CC   = 256;
static constexpr int NN   = 1024;
static constexpr int NB   = 4;      // first batches
static constexpr int NZ   = 12;     // (group-1)*b attention pairs
static constexpr int TOK  = NB * NN;

// Scratch layout (floats)
static constexpr long OFF_XQ   = 0;                        // 12*256*1024
static constexpr long OFF_XK   = OFF_XQ   + 3145728;       // 4*256*1024
static constexpr long OFF_XVT  = OFF_XK   + 1048576;       // 4*1024*256
static constexpr long OFF_E    = OFF_XVT  + 1048576;       // 12*1024*1024 (energy -> attn in place)
static constexpr long OFF_RT12 = OFF_E    + 12582912;      // 12*1024*256 (per-z attn@xv)
static constexpr long OFF_H    = OFF_RT12 + 3145728;       // 4096*256
static constexpr long OFF_H1   = OFF_H    + 1048576;       // 4096*1024
static constexpr long OFF_P4   = OFF_H1   + 4194304;       // 4*4096*256 (MLP2 split-K partials)
static constexpr long SCRATCH_TOTAL = OFF_P4 + 4194304;    // ~121.6 MB

__device__ float g_scratch[SCRATCH_TOTAL];

// ===========================================================================
// tf32 split helpers
// ===========================================================================
__device__ __forceinline__ float to_tf32(float v) {
    uint32_t u;
    asm("cvt.rna.tf32.f32 %0, %1;" : "=r"(u) : "f"(v));
    return __uint_as_float(u);
}
__device__ __forceinline__ void split_tf32(float v, float& hi, float& lo) {
    hi = to_tf32(v);
    lo = to_tf32(v - hi);
}

#define MMA_TF32(d, a, b) \
    asm("mma.sync.aligned.m16n8k8.row.col.f32.tf32.tf32.f32 " \
        "{%0,%1,%2,%3}, {%4,%5,%6,%7}, {%8,%9}, {%0,%1,%2,%3};" \
        : "+f"((d)[0]), "+f"((d)[1]), "+f"((d)[2]), "+f"((d)[3]) \
        : "r"((a)[0]), "r"((a)[1]), "r"((a)[2]), "r"((a)[3]), \
          "r"((b)[0]), "r"((b)[1]))

// ===========================================================================
// Tensor-core fp32 GEMM via tf32x3:  C[m][n] = alpha * sum_k opA[k][m]*opB[k][n]
//   AKM=true : A stored (K, M) row-major (m contiguous)
//   AKM=false: A stored (M, K) row-major -> transpose on smem store
//   (same for B/N). 128x128x16 tiles, 8 warps (2m x 4n), warp tile 64x32.
// Requires M%128==0, N%128==0, K%16==0, leading dims %4==0.
// ===========================================================================
template<bool AKM, bool BKM>
__global__ void __launch_bounds__(256)
gemm_tc(const float* __restrict__ A, const float* __restrict__ B, float* __restrict__ C,
        int K, int lda, int ldb, int ldc,
        long asb, long bsb, long csb, int aMod, int bMod,
        float alpha, const float* __restrict__ bias,
        const float* __restrict__ res, int relu)
{
    constexpr int BM = 128, BN = 128, BK = 16;
    constexpr int SROW = BM + 8;   // 136 floats: 136 % 32 == 8 -> conflict-free frag loads
    __shared__ float As[2][BK][SROW];   // [hi/lo][k][m]
    __shared__ float Bs[2][BK][SROW];   // [hi/lo][k][n]

    const int z = blockIdx.z;
    const float* Ab = A + (long)(aMod ? (z % aMod) : z) * asb;
    const float* Bb = B + (long)(bMod ? (z % bMod) : z) * bsb;
    float* Cb = C + (long)z * csb;
    const float* Rb = res ? (res + (long)z * csb) : nullptr;

    const int bm = blockIdx.y * BM;
    const int bn = blockIdx.x * BN;
    const int tid  = threadIdx.x;
    const int lane = tid & 31, warp = tid >> 5;
    const int g = lane >> 2, t = lane & 3;
    const int wm = (warp >> 2) * 64;   // 0 or 64
    const int wn = (warp & 3) * 32;    // 0,32,64,96

    float acc[4][4][4];
#pragma unroll
    for (int i = 0; i < 4; i++)
#pragma unroll
        for (int j = 0; j < 4; j++)
#pragma unroll
            for (int c = 0; c < 4; c++) acc[i][j][c] = 0.f;

    for (int kt = 0; kt < K; kt += BK) {
        // ---- load + split A tile ----
        if (AKM) {
#pragma unroll
            for (int v = tid; v < BK * BM / 4; v += 256) {
                int kk = v >> 5;             // BM/4 = 32
                int mv = (v & 31) << 2;
                float4 tv = *(const float4*)(Ab + (long)(kt + kk) * lda + bm + mv);
                float4 h4, l4;
                split_tf32(tv.x, h4.x, l4.x); split_tf32(tv.y, h4.y, l4.y);
                split_tf32(tv.z, h4.z, l4.z); split_tf32(tv.w, h4.w, l4.w);
                *(float4*)&As[0][kk][mv] = h4;
                *(float4*)&As[1][kk][mv] = l4;
            }
        } else {
#pragma unroll
            for (int v = tid; v < BK * BM / 4; v += 256) {
                int mm = v >> 2;             // BK/4 = 4
                int kv = (v & 3) << 2;
                float4 tv = *(const float4*)(Ab + (long)(bm + mm) * lda + kt + kv);
                float h, l;
                split_tf32(tv.x, h, l); As[0][kv+0][mm] = h; As[1][kv+0][mm] = l;
                split_tf32(tv.y, h, l); As[0][kv+1][mm] = h; As[1][kv+1][mm] = l;
                split_tf32(tv.z, h, l); As[0][kv+2][mm] = h; As[1][kv+2][mm] = l;
                split_tf32(tv.w, h, l); As[0][kv+3][mm] = h; As[1][kv+3][mm] = l;
            }
        }
        // ---- load + split B tile ----
        if (BKM) {
#pragma unroll
            for (int v = tid; v < BK * BN / 4; v += 256) {
                int kk = v >> 5;
                int nv = (v & 31) << 2;
                float4 tv = *(const float4*)(Bb + (long)(kt + kk) * ldb + bn + nv);
                float4 h4, l4;
                split_tf32(tv.x, h4.x, l4.x); split_tf32(tv.y, h4.y, l4.y);
                split_tf32(tv.z, h4.z, l4.z); split_tf32(tv.w, h4.w, l4.w);
                *(float4*)&Bs[0][kk][nv] = h4;
                *(float4*)&Bs[1][kk][nv] = l4;
            }
        } else {
#pragma unroll
            for (int v = tid; v < BK * BN / 4; v += 256) {
                int nn = v >> 2;
                int kv = (v & 3) << 2;
                float4 tv = *(const float4*)(Bb + (long)(bn + nn) * ldb + kt + kv);
                float h, l;
                split_tf32(tv.x, h, l); Bs[0][kv+0][nn] = h; Bs[1][kv+0][nn] = l;
                split_tf32(tv.y, h, l); Bs[0][kv+1][nn] = h; Bs[1][kv+1][nn] = l;
                split_tf32(tv.z, h, l); Bs[0][kv+2][nn] = h; Bs[1][kv+2][nn] = l;
                split_tf32(tv.w, h, l); Bs[0][kv+3][nn] = h; Bs[1][kv+3][nn] = l;
            }
        }
        __syncthreads();

#pragma unroll
        for (int ks = 0; ks < BK; ks += 8) {
            // B fragments for this k8 step (all 4 n-frags, hi+lo)
            uint32_t bh[4][2], bl[4][2];
#pragma unroll
            for (int fn = 0; fn < 4; fn++) {
                int n = wn + fn * 8 + g;
                bh[fn][0] = __float_as_uint(Bs[0][ks + t    ][n]);
                bh[fn][1] = __float_as_uint(Bs[0][ks + t + 4][n]);
                bl[fn][0] = __float_as_uint(Bs[1][ks + t    ][n]);
                bl[fn][1] = __float_as_uint(Bs[1][ks + t + 4][n]);
            }
#pragma unroll
            for (int fm = 0; fm < 4; fm++) {
                int m = wm + fm * 16 + g;
                uint32_t ah[4], al[4];
                ah[0] = __float_as_uint(As[0][ks + t    ][m]);
                ah[1] = __float_as_uint(As[0][ks + t    ][m + 8]);
                ah[2] = __float_as_uint(As[0][ks + t + 4][m]);
                ah[3] = __float_as_uint(As[0][ks + t + 4][m + 8]);
                al[0] = __float_as_uint(As[1][ks + t    ][m]);
                al[1] = __float_as_uint(As[1][ks + t    ][m + 8]);
                al[2] = __float_as_uint(As[1][ks + t + 4][m]);
                al[3] = __float_as_uint(As[1][ks + t + 4][m + 8]);
#pragma unroll
                for (int fn = 0; fn < 4; fn++) {
                    MMA_TF32(acc[fm][fn], al, bh[fn]);   // lo*hi
                    MMA_TF32(acc[fm][fn], ah, bl[fn]);   // hi*lo
                    MMA_TF32(acc[fm][fn], ah, bh[fn]);   // hi*hi
                }
            }
        }
        __syncthreads();
    }

    // ---- epilogue ----
#pragma unroll
    for (int fm = 0; fm < 4; fm++) {
        int r0 = bm + wm + fm * 16 + g;
        int r1 = r0 + 8;
#pragma unroll
        for (int fn = 0; fn < 4; fn++) {
            int cn = bn + wn + fn * 8 + 2 * t;
            float v0 = acc[fm][fn][0] * alpha;
            float v1 = acc[fm][fn][1] * alpha;
            float v2 = acc[fm][fn][2] * alpha;
            float v3 = acc[fm][fn][3] * alpha;
            if (bias) { float b0 = bias[cn], b1x = bias[cn + 1];
                        v0 += b0; v1 += b1x; v2 += b0; v3 += b1x; }
            if (Rb)   { v0 += Rb[(long)r0 * ldc + cn];
                        v1 += Rb[(long)r0 * ldc + cn + 1];
                        v2 += Rb[(long)r1 * ldc + cn];
                        v3 += Rb[(long)r1 * ldc + cn + 1]; }
            if (relu) { v0 = fmaxf(v0, 0.f); v1 = fmaxf(v1, 0.f);
                        v2 = fmaxf(v2, 0.f); v3 = fmaxf(v3, 0.f); }
            *(float2*)(Cb + (long)r0 * ldc + cn) = make_float2(v0, v1);
            *(float2*)(Cb + (long)r1 * ldc + cn) = make_float2(v2, v3);
        }
    }
}

// ===========================================================================
// FFMA GEMM (kept for the small xq/xk convs where M=64 per batch)
// ===========================================================================
template<int BM, int BN, int BK, int TM, int TN, bool AKM, bool BKM, int PA, int PB>
__global__ void __launch_bounds__((BM/TM)*(BN/TN))
gemm_k(const float* __restrict__ A, const float* __restrict__ B, float* __restrict__ C,
       int K, int lda, int ldb, int ldc,
       long asb, long bsb, long csb, int aMod, int bMod,
       float alpha, const float* __restrict__ bias,
       const float* __restrict__ res, int relu)
{
    constexpr int NT = (BM/TM)*(BN/TN);
    const int z = blockIdx.z;
    const float* Ab = A + (aMod ? (long)(z % aMod) * asb : (long)z * asb);
    const float* Bb = B + (bMod ? (long)(z % bMod) * bsb : (long)z * bsb);
    float* Cb = C + (long)z * csb;
    const float* Rb = res ? (res + (long)z * csb) : nullptr;

    const int bm = blockIdx.y * BM;
    const int bn = blockIdx.x * BN;

    __shared__ float As[BK][BM + PA];
    __shared__ float Bs[BK][BN + PB];

    const int tid = threadIdx.x;
    const int tx = tid % (BN / TN);
    const int ty = tid / (BN / TN);

    float acc[TM][TN];
#pragma unroll
    for (int i = 0; i < TM; i++)
#pragma unroll
        for (int j = 0; j < TN; j++) acc[i][j] = 0.f;

    for (int kt = 0; kt < K; kt += BK) {
        if (AKM) {
#pragma unroll
            for (int v = tid; v < BK * BM / 4; v += NT) {
                int kk = v / (BM / 4), mv = v % (BM / 4);
                float4 tv = *(const float4*)(Ab + (long)(kt + kk) * lda + bm + mv * 4);
                *(float4*)&As[kk][mv * 4] = tv;
            }
        } else {
#pragma unroll
            for (int v = tid; v < BK * BM / 4; v += NT) {
                int mm = v / (BK / 4), kv = v % (BK / 4);
                float4 tv = *(const float4*)(Ab + (long)(bm + mm) * lda + kt + kv * 4);
                As[kv * 4 + 0][mm] = tv.x;
                As[kv * 4 + 1][mm] = tv.y;
                As[kv * 4 + 2][mm] = tv.z;
                As[kv * 4 + 3][mm] = tv.w;
            }
        }
        if (BKM) {
#pragma unroll
            for (int v = tid; v < BK * BN / 4; v += NT) {
                int kk = v / (BN / 4), nv = v % (BN / 4);
                float4 tv = *(const float4*)(Bb + (long)(kt + kk) * ldb + bn + nv * 4);
                *(float4*)&Bs[kk][nv * 4] = tv;
            }
        } else {
#pragma unroll
            for (int v = tid; v < BK * BN / 4; v += NT) {
                int nn = v / (BK / 4), kv = v % (BK / 4);
                float4 tv = *(const float4*)(Bb + (long)(bn + nn) * ldb + kt + kv * 4);
                Bs[kv * 4 + 0][nn] = tv.x;
                Bs[kv * 4 + 1][nn] = tv.y;
                Bs[kv * 4 + 2][nn] = tv.z;
                Bs[kv * 4 + 3][nn] = tv.w;
            }
        }
        __syncthreads();

#pragma unroll
        for (int kk = 0; kk < BK; kk++) {
            float a[TM], bfr[TN];
            float4 a0 = *(const float4*)&As[kk][ty * TM];
            float4 a1 = *(const float4*)&As[kk][ty * TM + 4];
            a[0]=a0.x; a[1]=a0.y; a[2]=a0.z; a[3]=a0.w;
            a[4]=a1.x; a[5]=a1.y; a[6]=a1.z; a[7]=a1.w;
            float4 b0 = *(const float4*)&Bs[kk][tx * TN];
            float4 b1 = *(const float4*)&Bs[kk][tx * TN + 4];
            bfr[0]=b0.x; bfr[1]=b0.y; bfr[2]=b0.z; bfr[3]=b0.w;
            bfr[4]=b1.x; bfr[5]=b1.y; bfr[6]=b1.z; bfr[7]=b1.w;
#pragma unroll
            for (int i = 0; i < TM; i++)
#pragma unroll
                for (int j = 0; j < TN; j++)
                    acc[i][j] = fmaf(a[i], bfr[j], acc[i][j]);
        }
        __syncthreads();
    }

#pragma unroll
    for (int i = 0; i < TM; i++) {
        int cm = bm + ty * TM + i;
#pragma unroll
        for (int j = 0; j < TN; j++) {
            int cn = bn + tx * TN + j;
            float v = acc[i][j] * alpha;
            if (bias) v += bias[cn];
            if (Rb)   v += Rb[(long)cm * ldc + cn];
            if (relu) v = fmaxf(v, 0.f);
            Cb[(long)cm * ldc + cn] = v;
        }
    }
}

// ===========================================================================
// In-place row softmax over last dim of E[z][n][1024]
// ===========================================================================
__global__ void softmax_inplace_k(float* __restrict__ E)
{
    const int n = blockIdx.x;
    const int z = blockIdx.y;
    float* row = E + ((long)z * NN + n) * NN;
    const int tid = threadIdx.x;  // 256

    float e[4];
#pragma unroll
    for (int k = 0; k < 4; k++) e[k] = row[tid + 256 * k];

    __shared__ float red[256];
    float m = fmaxf(fmaxf(e[0], e[1]), fmaxf(e[2], e[3]));
    red[tid] = m; __syncthreads();
    for (int s = 128; s > 0; s >>= 1) {
        if (tid < s) red[tid] = fmaxf(red[tid], red[tid + s]);
        __syncthreads();
    }
    m = red[0]; __syncthreads();

    float ssum = 0.f;
#pragma unroll
    for (int k = 0; k < 4; k++) { e[k] = expf(e[k] - m); ssum += e[k]; }
    red[tid] = ssum; __syncthreads();
    for (int s = 128; s > 0; s >>= 1) {
        if (tid < s) red[tid] += red[tid + s];
        __syncthreads();
    }
    float inv = 1.f / red[0];
#pragma unroll
    for (int k = 0; k < 4; k++) row[tid + 256 * k] = e[k] * inv;
}

// ===========================================================================
// LN1 (fused 3-way mean of Rt12 + residual): h[t][c] = LN_c(x[b][c][n] + xr)
// ===========================================================================
__global__ void ln1_k(const float* __restrict__ x, const float* __restrict__ Rt12,
                      const float* __restrict__ gam, const float* __restrict__ bet,
                      float* __restrict__ h)
{
    const int t = blockIdx.x;
    const int b = t >> 10, n = t & 1023;
    const int c = threadIdx.x;
    long base = ((long)(3 * b) * NN + n) * CC + c;
    float r = Rt12[base] + Rt12[base + (long)NN * CC] + Rt12[base + 2L * NN * CC];
    float v = x[((long)b * CC + c) * NN + n] + r * (1.f / 48.f);

    __shared__ float red[256];
    red[c] = v; __syncthreads();
    for (int s = 128; s > 0; s >>= 1) { if (c < s) red[c] += red[c + s]; __syncthreads(); }
    float mu = red[0] * (1.f / CC); __syncthreads();
    float d = v - mu;
    red[c] = d * d; __syncthreads();
    for (int s = 128; s > 0; s >>= 1) { if (c < s) red[c] += red[c + s]; __syncthreads(); }
    float var = red[0] * (1.f / CC);
    h[(long)t * CC + c] = d * rsqrtf(var + 1e-6f) * gam[c] + bet[c];
}

// ===========================================================================
// LN2 (fused MLP2 split-K reduce + bias + residual) + relu + transposed write
// ===========================================================================
__global__ void ln2_out_k(const float* __restrict__ P4, const float* __restrict__ h,
                          const float* __restrict__ b2,
                          const float* __restrict__ gam, const float* __restrict__ bet,
                          float* __restrict__ out)
{
    const int t = blockIdx.x;
    const int b = t >> 10, n = t & 1023;
    const int c = threadIdx.x;
    long idx = (long)t * CC + c;
    float v = h[idx] + b2[c];
#pragma unroll
    for (int z = 0; z < 4; z++) v += P4[(long)z * TOK * CC + idx];

    __shared__ float red[256];
    red[c] = v; __syncthreads();
    for (int s = 128; s > 0; s >>= 1) { if (c < s) red[c] += red[c + s]; __syncthreads(); }
    float mu = red[0] * (1.f / CC); __syncthreads();
    float d = v - mu;
    red[c] = d * d; __syncthreads();
    for (int s = 128; s > 0; s >>= 1) { if (c < s) red[c] += red[c + s]; __syncthreads(); }
    float var = red[0] * (1.f / CC);
    float hv = d * rsqrtf(var + 1e-6f) * gam[c] + bet[c];
    out[((long)b * CC + c) * NN + n] = fmaxf(hv, 0.f);
}

// ===========================================================================
extern "C" void kernel_launch(void* const* d_in, const int* in_sizes, int n_in,
                              void* d_out, int out_size)
{
    (void)in_sizes; (void)n_in; (void)out_size;
    const float* x     = (const float*)d_in[0];
    const float* Wq    = (const float*)d_in[1];
    const float* Wk    = (const float*)d_in[2];
    const float* Wv    = (const float*)d_in[3];
    const float* bv    = (const float*)d_in[4];
    const float* ln1_g = (const float*)d_in[5];
    const float* ln1_b = (const float*)d_in[6];
    const float* W1    = (const float*)d_in[7];
    const float* b1    = (const float*)d_in[8];
    const float* W2    = (const float*)d_in[9];
    const float* b2    = (const float*)d_in[10];
    const float* ln2_g = (const float*)d_in[11];
    const float* ln2_b = (const float*)d_in[12];
    float* out = (float*)d_out;

    float* S = nullptr;
    cudaGetSymbolAddress((void**)&S, g_scratch);
    float* xq   = S + OFF_XQ;
    float* xk   = S + OFF_XK;
    float* xvT  = S + OFF_XVT;
    float* E    = S + OFF_E;
    float* Rt12 = S + OFF_RT12;
    float* h    = S + OFF_H;
    float* H1   = S + OFF_H1;
    float* P4   = S + OFF_P4;

    const float* xlast = x + (long)NB * CC * NN;

    // out[4:] = last (unchanged)
    cudaMemcpyAsync(out + (long)NB * CC * NN, xlast,
                    (size_t)12 * CC * NN * sizeof(float),
                    cudaMemcpyDeviceToDevice, 0);

    // xq[z=(B,s)][o][n] = Wq[s] @ last[B, s*64.., :]  (48 batches 64x1024x64, FFMA)
    gemm_k<64,128,16,8,8,false,true,4,0><<<dim3(8,1,48),128>>>(
        Wq, xlast, xq, 64, 64, NN, NN,
        (long)64*64, (long)64*NN, (long)64*NN, 4, 0,
        1.f, nullptr, nullptr, 0);

    // xk: 16 batches 64x1024x64 over first (FFMA)
    gemm_k<64,128,16,8,8,false,true,4,0><<<dim3(8,1,16),128>>>(
        Wk, x, xk, 64, 64, NN, NN,
        (long)64*64, (long)64*NN, (long)64*NN, 4, 0,
        1.f, nullptr, nullptr, 0);

    // xvT[b][n][c] = (Wv @ x[b])^T + bv   (4 batches 1024x256x256, TC)
    gemm_tc<true,false><<<dim3(2,8,4),256>>>(
        x, Wv, xvT, CC, NN, CC, CC,
        (long)CC*NN, 0L, (long)NN*CC, 0, 0,
        1.f, bv, nullptr, 0);

    // energy: E[z][n][m] = sum_ch xq[z][ch][n] * xk[z%4][ch][m]  (12 x 1024x1024x256, TC)
    gemm_tc<true,true><<<dim3(8,8,12),256>>>(
        xq, xk, E, CC, NN, NN, NN,
        (long)CC*NN, (long)CC*NN, (long)NN*NN, 0, 4,
        1.f, nullptr, nullptr, 0);

    // softmax rows in place
    softmax_inplace_k<<<dim3(NN, NZ), 256>>>(E);

    // per-z apply: Rt12[z][m][c] = sum_k attn[z][k][m] * xvT[z%4][k][c]  (12 x 1024x256x1024, TC)
    gemm_tc<true,true><<<dim3(2,8,12),256>>>(
        E, xvT, Rt12, NN, NN, CC, CC,
        (long)NN*NN, (long)NN*CC, (long)NN*CC, 0, 4,
        1.f, nullptr, nullptr, 0);

    // LN1 (3-way mean * 1/48 + residual fused)
    ln1_k<<<TOK, 256>>>(x, Rt12, ln1_g, ln1_b, h);

    // MLP1: H1 = relu(h @ W1^T + b1)   (4096x1024x256, TC)
    gemm_tc<false,false><<<dim3(8,32,1),256>>>(
        h, W1, H1, CC, CC, CC, 4*CC,
        0L, 0L, 0L, 0, 0,
        1.f, b1, nullptr, 1);

    // MLP2 split-K (4 chunks of K=256): P4[z] = H1[:, z*256:+256] @ W2[:, z*256:+256]^T
    gemm_tc<false,false><<<dim3(2,32,4),256>>>(
        H1, W2, P4, CC, 4*CC, 4*CC, CC,
        256L, 256L, (long)TOK*CC, 0, 0,
        1.f, nullptr, nullptr, 0);

    // LN2 (split-K reduce + b2 + residual h fused) + relu + transpose into out[:4]
    ln2_out_k<<<TOK, 256>>>(P4, h, b2, ln2_g, ln2_b, out);
}

// round 13
// speedup vs baseline: 1.7823x; 1.1094x over previous
#include <cuda_runtime.h>
#include <math.h>
#include <stdint.h>

// Problem constants: x (16, 256, 1024); first = x[:4], last = x[4:]
static constexpr int CC   = 256;
static constexpr int NN   = 1024;
static constexpr int NB   = 4;      // first batches
static constexpr int NZ   = 12;     // (group-1)*b attention pairs
static constexpr int TOK  = NB * NN;

// Scratch layout (floats)
static constexpr long OFF_XQ   = 0;                        // 12*256*1024
static constexpr long OFF_XK   = OFF_XQ   + 3145728;       // 4*256*1024
static constexpr long OFF_XVT  = OFF_XK   + 1048576;       // 4*1024*256
static constexpr long OFF_E    = OFF_XVT  + 1048576;       // 12*1024*1024 (energy -> attn in place)
static constexpr long OFF_RT12 = OFF_E    + 12582912;      // 12*1024*256 (per-z attn@xv)
static constexpr long OFF_H    = OFF_RT12 + 3145728;       // 4096*256
static constexpr long OFF_H1   = OFF_H    + 1048576;       // 4096*1024
static constexpr long OFF_P4   = OFF_H1   + 4194304;       // 4*4096*256 (MLP2 split-K partials)
static constexpr long SCRATCH_TOTAL = OFF_P4 + 4194304;    // ~121.6 MB

__device__ float g_scratch[SCRATCH_TOTAL];

// ===========================================================================
// tf32 split helpers
// ===========================================================================
__device__ __forceinline__ float to_tf32(float v) {
    uint32_t u;
    asm("cvt.rna.tf32.f32 %0, %1;" : "=r"(u) : "f"(v));
    return __uint_as_float(u);
}
__device__ __forceinline__ void split_tf32(float v, float& hi, float& lo) {
    hi = to_tf32(v);
    lo = to_tf32(v - hi);
}

#define MMA_TF32(d, a, b) \
    asm("mma.sync.aligned.m16n8k8.row.col.f32.tf32.tf32.f32 " \
        "{%0,%1,%2,%3}, {%4,%5,%6,%7}, {%8,%9}, {%0,%1,%2,%3};" \
        : "+f"((d)[0]), "+f"((d)[1]), "+f"((d)[2]), "+f"((d)[3]) \
        : "r"((a)[0]), "r"((a)[1]), "r"((a)[2]), "r"((a)[3]), \
          "r"((b)[0]), "r"((b)[1]))

// ===========================================================================
// Tensor-core fp32 GEMM via tf32x3, DOUBLE-BUFFERED:
//   C[m][n] = alpha * sum_k opA[k][m]*opB[k][n]
//   AKM=true : A stored (K, M) row-major (m contiguous)
//   AKM=false: A stored (M, K) row-major -> transpose on smem store
//   (same for B/N). 128x128x16 tiles, 8 warps (2m x 4n), warp tile 64x32.
// Dynamic smem: 2 stages x (hi,lo) x BK x SROW for A and B = 69632 bytes.
// Requires M%128==0, N%128==0, K%32==0, leading dims %4==0.
// ===========================================================================
template<bool AKM, bool BKM>
__global__ void __launch_bounds__(256)
gemm_tc(const float* __restrict__ A, const float* __restrict__ B, float* __restrict__ C,
        int K, int lda, int ldb, int ldc,
        long asb, long bsb, long csb, int aMod, int bMod,
        float alpha, const float* __restrict__ bias,
        const float* __restrict__ res, int relu)
{
    constexpr int BM = 128, BN = 128, BK = 16;
    constexpr int SROW = BM + 8;                 // 136: frag LDS conflict-free
    constexpr int STG  = 2 * BK * SROW;          // floats per (stage) incl hi+lo? no: per plane
    // layout: SA[stage][hl][k][m] ; SB same after A region
    extern __shared__ float sm[];
    float* SA = sm;
    float* SB = sm + 2 * 2 * BK * SROW;          // 8704 floats offset

    const int z = blockIdx.z;
    const float* Ab = A + (long)(aMod ? (z % aMod) : z) * asb;
    const float* Bb = B + (long)(bMod ? (z % bMod) : z) * bsb;
    float* Cb = C + (long)z * csb;
    const float* Rb = res ? (res + (long)z * csb) : nullptr;

    const int bm = blockIdx.y * BM;
    const int bn = blockIdx.x * BN;
    const int tid  = threadIdx.x;
    const int lane = tid & 31, warp = tid >> 5;
    const int g = lane >> 2, t = lane & 3;
    const int wm = (warp >> 2) * 64;   // 0 or 64
    const int wn = (warp & 3) * 32;    // 0,32,64,96

    float acc[4][4][4];
#pragma unroll
    for (int i = 0; i < 4; i++)
#pragma unroll
        for (int j = 0; j < 4; j++)
#pragma unroll
            for (int c = 0; c < 4; c++) acc[i][j][c] = 0.f;

    float4 ra[2], rb[2];

    auto fetch = [&](int kt) {
#pragma unroll
        for (int i = 0; i < 2; i++) {
            int v = tid + i * 256;
            if (AKM) {
                int kk = v >> 5, mv = (v & 31) << 2;
                ra[i] = *(const float4*)(Ab + (long)(kt + kk) * lda + bm + mv);
            } else {
                int mm = v >> 2, kv = (v & 3) << 2;
                ra[i] = *(const float4*)(Ab + (long)(bm + mm) * lda + kt + kv);
            }
            if (BKM) {
                int kk = v >> 5, nv = (v & 31) << 2;
                rb[i] = *(const float4*)(Bb + (long)(kt + kk) * ldb + bn + nv);
            } else {
                int nn = v >> 2, kv = (v & 3) << 2;
                rb[i] = *(const float4*)(Bb + (long)(bn + nn) * ldb + kt + kv);
            }
        }
    };

    auto store = [&](int st) {
        float* AH = SA + (st * 2 + 0) * BK * SROW;
        float* AL = SA + (st * 2 + 1) * BK * SROW;
        float* BH = SB + (st * 2 + 0) * BK * SROW;
        float* BL = SB + (st * 2 + 1) * BK * SROW;
#pragma unroll
        for (int i = 0; i < 2; i++) {
            int v = tid + i * 256;
            if (AKM) {
                int kk = v >> 5, mv = (v & 31) << 2;
                float4 h4, l4;
                split_tf32(ra[i].x, h4.x, l4.x); split_tf32(ra[i].y, h4.y, l4.y);
                split_tf32(ra[i].z, h4.z, l4.z); split_tf32(ra[i].w, h4.w, l4.w);
                *(float4*)(AH + kk * SROW + mv) = h4;
                *(float4*)(AL + kk * SROW + mv) = l4;
            } else {
                int mm = v >> 2, kv = (v & 3) << 2;
                float h, l;
                split_tf32(ra[i].x, h, l); AH[(kv+0)*SROW+mm] = h; AL[(kv+0)*SROW+mm] = l;
                split_tf32(ra[i].y, h, l); AH[(kv+1)*SROW+mm] = h; AL[(kv+1)*SROW+mm] = l;
                split_tf32(ra[i].z, h, l); AH[(kv+2)*SROW+mm] = h; AL[(kv+2)*SROW+mm] = l;
                split_tf32(ra[i].w, h, l); AH[(kv+3)*SROW+mm] = h; AL[(kv+3)*SROW+mm] = l;
            }
            if (BKM) {
                int kk = v >> 5, nv = (v & 31) << 2;
                float4 h4, l4;
                split_tf32(rb[i].x, h4.x, l4.x); split_tf32(rb[i].y, h4.y, l4.y);
                split_tf32(rb[i].z, h4.z, l4.z); split_tf32(rb[i].w, h4.w, l4.w);
                *(float4*)(BH + kk * SROW + nv) = h4;
                *(float4*)(BL + kk * SROW + nv) = l4;
            } else {
                int nn = v >> 2, kv = (v & 3) << 2;
                float h, l;
                split_tf32(rb[i].x, h, l); BH[(kv+0)*SROW+nn] = h; BL[(kv+0)*SROW+nn] = l;
                split_tf32(rb[i].y, h, l); BH[(kv+1)*SROW+nn] = h; BL[(kv+1)*SROW+nn] = l;
                split_tf32(rb[i].z, h, l); BH[(kv+2)*SROW+nn] = h; BL[(kv+2)*SROW+nn] = l;
                split_tf32(rb[i].w, h, l); BH[(kv+3)*SROW+nn] = h; BL[(kv+3)*SROW+nn] = l;
            }
        }
    };

    // prologue: tile 0 -> stage 0
    fetch(0);
    store(0);
    __syncthreads();

    const int ntiles = K / BK;
    for (int tt = 0; tt < ntiles; tt++) {
        if (tt + 1 < ntiles) fetch((tt + 1) * BK);  // LDG early, hidden under MMAs

        const int st = tt & 1;
        const float* AH = SA + (st * 2 + 0) * BK * SROW;
        const float* AL = SA + (st * 2 + 1) * BK * SROW;
        const float* BH = SB + (st * 2 + 0) * BK * SROW;
        const float* BL = SB + (st * 2 + 1) * BK * SROW;

#pragma unroll
        for (int ks = 0; ks < BK; ks += 8) {
            uint32_t bh[4][2], bl[4][2];
#pragma unroll
            for (int fn = 0; fn < 4; fn++) {
                int n = wn + fn * 8 + g;
                bh[fn][0] = __float_as_uint(BH[(ks + t    ) * SROW + n]);
                bh[fn][1] = __float_as_uint(BH[(ks + t + 4) * SROW + n]);
                bl[fn][0] = __float_as_uint(BL[(ks + t    ) * SROW + n]);
                bl[fn][1] = __float_as_uint(BL[(ks + t + 4) * SROW + n]);
            }
#pragma unroll
            for (int fm = 0; fm < 4; fm++) {
                int m = wm + fm * 16 + g;
                uint32_t ah[4], al[4];
                ah[0] = __float_as_uint(AH[(ks + t    ) * SROW + m]);
                ah[1] = __float_as_uint(AH[(ks + t    ) * SROW + m + 8]);
                ah[2] = __float_as_uint(AH[(ks + t + 4) * SROW + m]);
                ah[3] = __float_as_uint(AH[(ks + t + 4) * SROW + m + 8]);
                al[0] = __float_as_uint(AL[(ks + t    ) * SROW + m]);
                al[1] = __float_as_uint(AL[(ks + t    ) * SROW + m + 8]);
                al[2] = __float_as_uint(AL[(ks + t + 4) * SROW + m]);
                al[3] = __float_as_uint(AL[(ks + t + 4) * SROW + m + 8]);
#pragma unroll
                for (int fn = 0; fn < 4; fn++) {
                    MMA_TF32(acc[fm][fn], al, bh[fn]);   // lo*hi
                    MMA_TF32(acc[fm][fn], ah, bl[fn]);   // hi*lo
                    MMA_TF32(acc[fm][fn], ah, bh[fn]);   // hi*hi
                }
            }
        }

        if (tt + 1 < ntiles) {
            store((tt + 1) & 1);   // other stage: safe vs current compute
            __syncthreads();       // one barrier per tile
        }
    }

    // ---- epilogue ----
#pragma unroll
    for (int fm = 0; fm < 4; fm++) {
        int r0 = bm + wm + fm * 16 + g;
        int r1 = r0 + 8;
#pragma unroll
        for (int fn = 0; fn < 4; fn++) {
            int cn = bn + wn + fn * 8 + 2 * t;
            float v0 = acc[fm][fn][0] * alpha;
            float v1 = acc[fm][fn][1] * alpha;
            float v2 = acc[fm][fn][2] * alpha;
            float v3 = acc[fm][fn][3] * alpha;
            if (bias) { float b0 = bias[cn], b1x = bias[cn + 1];
                        v0 += b0; v1 += b1x; v2 += b0; v3 += b1x; }
            if (Rb)   { v0 += Rb[(long)r0 * ldc + cn];
                        v1 += Rb[(long)r0 * ldc + cn + 1];
                        v2 += Rb[(long)r1 * ldc + cn];
                        v3 += Rb[(long)r1 * ldc + cn + 1]; }
            if (relu) { v0 = fmaxf(v0, 0.f); v1 = fmaxf(v1, 0.f);
                        v2 = fmaxf(v2, 0.f); v3 = fmaxf(v3, 0.f); }
            *(float2*)(Cb + (long)r0 * ldc + cn) = make_float2(v0, v1);
            *(float2*)(Cb + (long)r1 * ldc + cn) = make_float2(v2, v3);
        }
    }
}

static constexpr size_t GEMM_TC_SMEM = (size_t)(2 * 2 * 16 * 136) * 2 * sizeof(float); // 69632

// ===========================================================================
// FFMA GEMM (small xq/xk convs, M=64 per batch)
// ===========================================================================
template<int BM, int BN, int BK, int TM, int TN, bool AKM, bool BKM, int PA, int PB>
__global__ void __launch_bounds__((BM/TM)*(BN/TN))
gemm_k(const float* __restrict__ A, const float* __restrict__ B, float* __restrict__ C,
       int K, int lda, int ldb, int ldc,
       long asb, long bsb, long csb, int aMod, int bMod,
       float alpha, const float* __restrict__ bias,
       const float* __restrict__ res, int relu)
{
    constexpr int NT = (BM/TM)*(BN/TN);
    const int z = blockIdx.z;
    const float* Ab = A + (aMod ? (long)(z % aMod) * asb : (long)z * asb);
    const float* Bb = B + (bMod ? (long)(z % bMod) * bsb : (long)z * bsb);
    float* Cb = C + (long)z * csb;
    const float* Rb = res ? (res + (long)z * csb) : nullptr;

    const int bm = blockIdx.y * BM;
    const int bn = blockIdx.x * BN;

    __shared__ float As[BK][BM + PA];
    __shared__ float Bs[BK][BN + PB];

    const int tid = threadIdx.x;
    const int tx = tid % (BN / TN);
    const int ty = tid / (BN / TN);

    float acc[TM][TN];
#pragma unroll
    for (int i = 0; i < TM; i++)
#pragma unroll
        for (int j = 0; j < TN; j++) acc[i][j] = 0.f;

    for (int kt = 0; kt < K; kt += BK) {
        if (AKM) {
#pragma unroll
            for (int v = tid; v < BK * BM / 4; v += NT) {
                int kk = v / (BM / 4), mv = v % (BM / 4);
                float4 tv = *(const float4*)(Ab + (long)(kt + kk) * lda + bm + mv * 4);
                *(float4*)&As[kk][mv * 4] = tv;
            }
        } else {
#pragma unroll
            for (int v = tid; v < BK * BM / 4; v += NT) {
                int mm = v / (BK / 4), kv = v % (BK / 4);
                float4 tv = *(const float4*)(Ab + (long)(bm + mm) * lda + kt + kv * 4);
                As[kv * 4 + 0][mm] = tv.x;
                As[kv * 4 + 1][mm] = tv.y;
                As[kv * 4 + 2][mm] = tv.z;
                As[kv * 4 + 3][mm] = tv.w;
            }
        }
        if (BKM) {
#pragma unroll
            for (int v = tid; v < BK * BN / 4; v += NT) {
                int kk = v / (BN / 4), nv = v % (BN / 4);
                float4 tv = *(const float4*)(Bb + (long)(kt + kk) * ldb + bn + nv * 4);
                *(float4*)&Bs[kk][nv * 4] = tv;
            }
        } else {
#pragma unroll
            for (int v = tid; v < BK * BN / 4; v += NT) {
                int nn = v / (BK / 4), kv = v % (BK / 4);
                float4 tv = *(const float4*)(Bb + (long)(bn + nn) * ldb + kt + kv * 4);
                Bs[kv * 4 + 0][nn] = tv.x;
                Bs[kv * 4 + 1][nn] = tv.y;
                Bs[kv * 4 + 2][nn] = tv.z;
                Bs[kv * 4 + 3][nn] = tv.w;
            }
        }
        __syncthreads();

#pragma unroll
        for (int kk = 0; kk < BK; kk++) {
            float a[TM], bfr[TN];
            float4 a0 = *(const float4*)&As[kk][ty * TM];
            float4 a1 = *(const float4*)&As[kk][ty * TM + 4];
            a[0]=a0.x; a[1]=a0.y; a[2]=a0.z; a[3]=a0.w;
            a[4]=a1.x; a[5]=a1.y; a[6]=a1.z; a[7]=a1.w;
            float4 b0 = *(const float4*)&Bs[kk][tx * TN];
            float4 b1 = *(const float4*)&Bs[kk][tx * TN + 4];
            bfr[0]=b0.x; bfr[1]=b0.y; bfr[2]=b0.z; bfr[3]=b0.w;
            bfr[4]=b1.x; bfr[5]=b1.y; bfr[6]=b1.z; bfr[7]=b1.w;
#pragma unroll
            for (int i = 0; i < TM; i++)
#pragma unroll
                for (int j = 0; j < TN; j++)
                    acc[i][j] = fmaf(a[i], bfr[j], acc[i][j]);
        }
        __syncthreads();
    }

#pragma unroll
    for (int i = 0; i < TM; i++) {
        int cm = bm + ty * TM + i;
#pragma unroll
        for (int j = 0; j < TN; j++) {
            int cn = bn + tx * TN + j;
            float v = acc[i][j] * alpha;
            if (bias) v += bias[cn];
            if (Rb)   v += Rb[(long)cm * ldc + cn];
            if (relu) v = fmaxf(v, 0.f);
            Cb[(long)cm * ldc + cn] = v;
        }
    }
}

// ===========================================================================
// In-place row softmax over last dim of E[z][n][1024]
// ===========================================================================
__global__ void softmax_inplace_k(float* __restrict__ E)
{
    const int n = blockIdx.x;
    const int z = blockIdx.y;
    float* row = E + ((long)z * NN + n) * NN;
    const int tid = threadIdx.x;  // 256

    float e[4];
#pragma unroll
    for (int k = 0; k < 4; k++) e[k] = row[tid + 256 * k];

    __shared__ float red[256];
    float m = fmaxf(fmaxf(e[0], e[1]), fmaxf(e[2], e[3]));
    red[tid] = m; __syncthreads();
    for (int s = 128; s > 0; s >>= 1) {
        if (tid < s) red[tid] = fmaxf(red[tid], red[tid + s]);
        __syncthreads();
    }
    m = red[0]; __syncthreads();

    float ssum = 0.f;
#pragma unroll
    for (int k = 0; k < 4; k++) { e[k] = expf(e[k] - m); ssum += e[k]; }
    red[tid] = ssum; __syncthreads();
    for (int s = 128; s > 0; s >>= 1) {
        if (tid < s) red[tid] += red[tid + s];
        __syncthreads();
    }
    float inv = 1.f / red[0];
#pragma unroll
    for (int k = 0; k < 4; k++) row[tid + 256 * k] = e[k] * inv;
}

// ===========================================================================
// LN1 (fused 3-way mean of Rt12 + residual): h[t][c] = LN_c(x[b][c][n] + xr)
// ===========================================================================
__global__ void ln1_k(const float* __restrict__ x, const float* __restrict__ Rt12,
                      const float* __restrict__ gam, const float* __restrict__ bet,
                      float* __restrict__ h)
{
    const int t = blockIdx.x;
    const int b = t >> 10, n = t & 1023;
    const int c = threadIdx.x;
    long base = ((long)(3 * b) * NN + n) * CC + c;
    float r = Rt12[base] + Rt12[base + (long)NN * CC] + Rt12[base + 2L * NN * CC];
    float v = x[((long)b * CC + c) * NN + n] + r * (1.f / 48.f);

    __shared__ float red[256];
    red[c] = v; __syncthreads();
    for (int s = 128; s > 0; s >>= 1) { if (c < s) red[c] += red[c + s]; __syncthreads(); }
    float mu = red[0] * (1.f / CC); __syncthreads();
    float d = v - mu;
    red[c] = d * d; __syncthreads();
    for (int s = 128; s > 0; s >>= 1) { if (c < s) red[c] += red[c + s]; __syncthreads(); }
    float var = red[0] * (1.f / CC);
    h[(long)t * CC + c] = d * rsqrtf(var + 1e-6f) * gam[c] + bet[c];
}

// ===========================================================================
// LN2 (fused MLP2 split-K reduce + bias + residual) + relu + transposed write
// ===========================================================================
__global__ void ln2_out_k(const float* __restrict__ P4, const float* __restrict__ h,
                          const float* __restrict__ b2,
                          const float* __restrict__ gam, const float* __restrict__ bet,
                          float* __restrict__ out)
{
    const int t = blockIdx.x;
    const int b = t >> 10, n = t & 1023;
    const int c = threadIdx.x;
    long idx = (long)t * CC + c;
    float v = h[idx] + b2[c];
#pragma unroll
    for (int z = 0; z < 4; z++) v += P4[(long)z * TOK * CC + idx];

    __shared__ float red[256];
    red[c] = v; __syncthreads();
    for (int s = 128; s > 0; s >>= 1) { if (c < s) red[c] += red[c + s]; __syncthreads(); }
    float mu = red[0] * (1.f / CC); __syncthreads();
    float d = v - mu;
    red[c] = d * d; __syncthreads();
    for (int s = 128; s > 0; s >>= 1) { if (c < s) red[c] += red[c + s]; __syncthreads(); }
    float var = red[0] * (1.f / CC);
    float hv = d * rsqrtf(var + 1e-6f) * gam[c] + bet[c];
    out[((long)b * CC + c) * NN + n] = fmaxf(hv, 0.f);
}

// ===========================================================================
extern "C" void kernel_launch(void* const* d_in, const int* in_sizes, int n_in,
                              void* d_out, int out_size)
{
    (void)in_sizes; (void)n_in; (void)out_size;
    const float* x     = (const float*)d_in[0];
    const float* Wq    = (const float*)d_in[1];
    const float* Wk    = (const float*)d_in[2];
    const float* Wv    = (const float*)d_in[3];
    const float* bv    = (const float*)d_in[4];
    const float* ln1_g = (const float*)d_in[5];
    const float* ln1_b = (const float*)d_in[6];
    const float* W1    = (const float*)d_in[7];
    const float* b1    = (const float*)d_in[8];
    const float* W2    = (const float*)d_in[9];
    const float* b2    = (const float*)d_in[10];
    const float* ln2_g = (const float*)d_in[11];
    const float* ln2_b = (const float*)d_in[12];
    float* out = (float*)d_out;

    // raise dynamic smem cap for the TC kernels (host-side config; idempotent)
    cudaFuncSetAttribute(gemm_tc<true,true>,   cudaFuncAttributeMaxDynamicSharedMemorySize, (int)GEMM_TC_SMEM);
    cudaFuncSetAttribute(gemm_tc<true,false>,  cudaFuncAttributeMaxDynamicSharedMemorySize, (int)GEMM_TC_SMEM);
    cudaFuncSetAttribute(gemm_tc<false,false>, cudaFuncAttributeMaxDynamicSharedMemorySize, (int)GEMM_TC_SMEM);

    float* S = nullptr;
    cudaGetSymbolAddress((void**)&S, g_scratch);
    float* xq   = S + OFF_XQ;
    float* xk   = S + OFF_XK;
    float* xvT  = S + OFF_XVT;
    float* E    = S + OFF_E;
    float* Rt12 = S + OFF_RT12;
    float* h    = S + OFF_H;
    float* H1   = S + OFF_H1;
    float* P4   = S + OFF_P4;

    const float* xlast = x + (long)NB * CC * NN;

    // out[4:] = last (unchanged)
    cudaMemcpyAsync(out + (long)NB * CC * NN, xlast,
                    (size_t)12 * CC * NN * sizeof(float),
                    cudaMemcpyDeviceToDevice, 0);

    // xq[z=(B,s)][o][n] = Wq[s] @ last[B, s*64.., :]  (48 batches 64x1024x64, FFMA)
    gemm_k<64,128,16,8,8,false,true,4,0><<<dim3(8,1,48),128>>>(
        Wq, xlast, xq, 64, 64, NN, NN,
        (long)64*64, (long)64*NN, (long)64*NN, 4, 0,
        1.f, nullptr, nullptr, 0);

    // xk: 16 batches 64x1024x64 over first (FFMA)
    gemm_k<64,128,16,8,8,false,true,4,0><<<dim3(8,1,16),128>>>(
        Wk, x, xk, 64, 64, NN, NN,
        (long)64*64, (long)64*NN, (long)64*NN, 4, 0,
        1.f, nullptr, nullptr, 0);

    // xvT[b][n][c] = (Wv @ x[b])^T + bv   (4 batches 1024x256x256, TC)
    gemm_tc<true,false><<<dim3(2,8,4),256,GEMM_TC_SMEM>>>(
        x, Wv, xvT, CC, NN, CC, CC,
        (long)CC*NN, 0L, (long)NN*CC, 0, 0,
        1.f, bv, nullptr, 0);

    // energy: E[z][n][m] = sum_ch xq[z][ch][n] * xk[z%4][ch][m]  (12 x 1024x1024x256, TC)
    gemm_tc<true,true><<<dim3(8,8,12),256,GEMM_TC_SMEM>>>(
        xq, xk, E, CC, NN, NN, NN,
        (long)CC*NN, (long)CC*NN, (long)NN*NN, 0, 4,
        1.f, nullptr, nullptr, 0);

    // softmax rows in place
    softmax_inplace_k<<<dim3(NN, NZ), 256>>>(E);

    // per-z apply: Rt12[z][m][c] = sum_k attn[z][k][m] * xvT[z%4][k][c]  (12 x 1024x256x1024, TC)
    gemm_tc<true,true><<<dim3(2,8,12),256,GEMM_TC_SMEM>>>(
        E, xvT, Rt12, NN, NN, CC, CC,
        (long)NN*NN, (long)NN*CC, (long)NN*CC, 0, 4,
        1.f, nullptr, nullptr, 0);

    // LN1 (3-way mean * 1/48 + residual fused)
    ln1_k<<<TOK, 256>>>(x, Rt12, ln1_g, ln1_b, h);

    // MLP1: H1 = relu(h @ W1^T + b1)   (4096x1024x256, TC)
    gemm_tc<false,false><<<dim3(8,32,1),256,GEMM_TC_SMEM>>>(
        h, W1, H1, CC, CC, CC, 4*CC,
        0L, 0L, 0L, 0, 0,
        1.f, b1, nullptr, 1);

    // MLP2 split-K (4 chunks of K=256): P4[z] = H1[:, z*256:+256] @ W2[:, z*256:+256]^T
    gemm_tc<false,false><<<dim3(2,32,4),256,GEMM_TC_SMEM>>>(
        H1, W2, P4, CC, 4*CC, 4*CC, CC,
        256L, 256L, (long)TOK*CC, 0, 0,
        1.f, nullptr, nullptr, 0);

    // LN2 (split-K reduce + b2 + residual h fused) + relu + transpose into out[:4]
    ln2_out_k<<<TOK, 256>>>(P4, h, b2, ln2_g, ln2_b, out);
}

// round 14
// speedup vs baseline: 1.9321x; 1.0840x over previous
#include <cuda_runtime.h>
#include <math.h>
#include <stdint.h>

// Problem constants: x (16, 256, 1024); first = x[:4], last = x[4:]
static constexpr int CC   = 256;
static constexpr int NN   = 1024;
static constexpr int NB   = 4;      // first batches
static constexpr int NZ   = 12;     // (group-1)*b attention pairs
static constexpr int TOK  = NB * NN;

// Scratch layout (floats)
static constexpr long OFF_XQ   = 0;                        // 12*256*1024
static constexpr long OFF_XK   = OFF_XQ   + 3145728;       // 4*256*1024
static constexpr long OFF_XVT  = OFF_XK   + 1048576;       // 4*1024*256
static constexpr long OFF_E    = OFF_XVT  + 1048576;       // 12*1024*1024 (energy -> attn in place)
static constexpr long OFF_RT12 = OFF_E    + 12582912;      // 12*1024*256 (per-z attn@xv)
static constexpr long OFF_H    = OFF_RT12 + 3145728;       // 4096*256
static constexpr long OFF_H1   = OFF_H    + 1048576;       // 4096*1024
static constexpr long OFF_P4   = OFF_H1   + 4194304;       // 4*4096*256 (MLP2 split-K partials)
static constexpr long SCRATCH_TOTAL = OFF_P4 + 4194304;    // ~121.6 MB

__device__ float g_scratch[SCRATCH_TOTAL];

// ===========================================================================
// tf32 split helpers
// ===========================================================================
__device__ __forceinline__ float to_tf32(float v) {
    uint32_t u;
    asm("cvt.rna.tf32.f32 %0, %1;" : "=r"(u) : "f"(v));
    return __uint_as_float(u);
}
__device__ __forceinline__ void split_tf32(float v, float& hi, float& lo) {
    hi = to_tf32(v);
    lo = to_tf32(v - hi);
}

#define MMA_TF32(d, a, b) \
    asm("mma.sync.aligned.m16n8k8.row.col.f32.tf32.tf32.f32 " \
        "{%0,%1,%2,%3}, {%4,%5,%6,%7}, {%8,%9}, {%0,%1,%2,%3};" \
        : "+f"((d)[0]), "+f"((d)[1]), "+f"((d)[2]), "+f"((d)[3]) \
        : "r"((a)[0]), "r"((a)[1]), "r"((a)[2]), "r"((a)[3]), \
          "r"((b)[0]), "r"((b)[1]))

// ===========================================================================
// Tensor-core fp32 GEMM via tf32x3, double-buffered, 2 CTAs/SM:
//   C[m][n] = alpha * sum_k opA[k][m]*opB[k][n]
//   AKM=true : A stored (K, M) row-major (m contiguous)
//   AKM=false: A stored (M, K) row-major -> transpose on smem store
//   (same for B/N). 128x128x16 tiles, 8 warps (2m x 4n), warp tile 64x32.
// Dynamic smem: 2 stages x (hi,lo) x BK x SROW for A and B = 69632 bytes.
// Requires M%128==0, N%128==0, K%32==0, leading dims %4==0.
// ===========================================================================
template<bool AKM, bool BKM>
__global__ void __launch_bounds__(256, 2)
gemm_tc(const float* __restrict__ A, const float* __restrict__ B, float* __restrict__ C,
        int K, int lda, int ldb, int ldc,
        long asb, long bsb, long csb, int aMod, int bMod,
        float alpha, const float* __restrict__ bias,
        const float* __restrict__ res, int relu)
{
    constexpr int BM = 128, BN = 128, BK = 16;
    constexpr int SROW = BM + 8;                 // 136: frag LDS conflict-free
    // layout: SA[stage][hl][k][m] ; SB same after A region
    extern __shared__ float sm[];
    float* SA = sm;
    float* SB = sm + 2 * 2 * BK * SROW;          // 8704 floats offset

    const int z = blockIdx.z;
    const float* Ab = A + (long)(aMod ? (z % aMod) : z) * asb;
    const float* Bb = B + (long)(bMod ? (z % bMod) : z) * bsb;
    float* Cb = C + (long)z * csb;
    const float* Rb = res ? (res + (long)z * csb) : nullptr;

    const int bm = blockIdx.y * BM;
    const int bn = blockIdx.x * BN;
    const int tid  = threadIdx.x;
    const int lane = tid & 31, warp = tid >> 5;
    const int g = lane >> 2, t = lane & 3;
    const int wm = (warp >> 2) * 64;   // 0 or 64
    const int wn = (warp & 3) * 32;    // 0,32,64,96

    float acc[4][4][4];
#pragma unroll
    for (int i = 0; i < 4; i++)
#pragma unroll
        for (int j = 0; j < 4; j++)
#pragma unroll
            for (int c = 0; c < 4; c++) acc[i][j][c] = 0.f;

    float4 ra[2], rb[2];

    auto fetch = [&](int kt) {
#pragma unroll
        for (int i = 0; i < 2; i++) {
            int v = tid + i * 256;
            if (AKM) {
                int kk = v >> 5, mv = (v & 31) << 2;
                ra[i] = *(const float4*)(Ab + (long)(kt + kk) * lda + bm + mv);
            } else {
                int mm = v >> 2, kv = (v & 3) << 2;
                ra[i] = *(const float4*)(Ab + (long)(bm + mm) * lda + kt + kv);
            }
            if (BKM) {
                int kk = v >> 5, nv = (v & 31) << 2;
                rb[i] = *(const float4*)(Bb + (long)(kt + kk) * ldb + bn + nv);
            } else {
                int nn = v >> 2, kv = (v & 3) << 2;
                rb[i] = *(const float4*)(Bb + (long)(bn + nn) * ldb + kt + kv);
            }
        }
    };

    auto store = [&](int st) {
        float* AH = SA + (st * 2 + 0) * BK * SROW;
        float* AL = SA + (st * 2 + 1) * BK * SROW;
        float* BH = SB + (st * 2 + 0) * BK * SROW;
        float* BL = SB + (st * 2 + 1) * BK * SROW;
#pragma unroll
        for (int i = 0; i < 2; i++) {
            int v = tid + i * 256;
            if (AKM) {
                int kk = v >> 5, mv = (v & 31) << 2;
                float4 h4, l4;
                split_tf32(ra[i].x, h4.x, l4.x); split_tf32(ra[i].y, h4.y, l4.y);
                split_tf32(ra[i].z, h4.z, l4.z); split_tf32(ra[i].w, h4.w, l4.w);
                *(float4*)(AH + kk * SROW + mv) = h4;
                *(float4*)(AL + kk * SROW + mv) = l4;
            } else {
                int mm = v >> 2, kv = (v & 3) << 2;
                float h, l;
                split_tf32(ra[i].x, h, l); AH[(kv+0)*SROW+mm] = h; AL[(kv+0)*SROW+mm] = l;
                split_tf32(ra[i].y, h, l); AH[(kv+1)*SROW+mm] = h; AL[(kv+1)*SROW+mm] = l;
                split_tf32(ra[i].z, h, l); AH[(kv+2)*SROW+mm] = h; AL[(kv+2)*SROW+mm] = l;
                split_tf32(ra[i].w, h, l); AH[(kv+3)*SROW+mm] = h; AL[(kv+3)*SROW+mm] = l;
            }
            if (BKM) {
                int kk = v >> 5, nv = (v & 31) << 2;
                float4 h4, l4;
                split_tf32(rb[i].x, h4.x, l4.x); split_tf32(rb[i].y, h4.y, l4.y);
                split_tf32(rb[i].z, h4.z, l4.z); split_tf32(rb[i].w, h4.w, l4.w);
                *(float4*)(BH + kk * SROW + nv) = h4;
                *(float4*)(BL + kk * SROW + nv) = l4;
            } else {
                int nn = v >> 2, kv = (v & 3) << 2;
                float h, l;
                split_tf32(rb[i].x, h, l); BH[(kv+0)*SROW+nn] = h; BL[(kv+0)*SROW+nn] = l;
                split_tf32(rb[i].y, h, l); BH[(kv+1)*SROW+nn] = h; BL[(kv+1)*SROW+nn] = l;
                split_tf32(rb[i].z, h, l); BH[(kv+2)*SROW+nn] = h; BL[(kv+2)*SROW+nn] = l;
                split_tf32(rb[i].w, h, l); BH[(kv+3)*SROW+nn] = h; BL[(kv+3)*SROW+nn] = l;
            }
        }
    };

    // prologue: tile 0 -> stage 0
    fetch(0);
    store(0);
    __syncthreads();

    const int ntiles = K / BK;
    for (int tt = 0; tt < ntiles; tt++) {
        if (tt + 1 < ntiles) fetch((tt + 1) * BK);  // LDG early, hidden under MMAs

        const int st = tt & 1;
        const float* AH = SA + (st * 2 + 0) * BK * SROW;
        const float* AL = SA + (st * 2 + 1) * BK * SROW;
        const float* BH = SB + (st * 2 + 0) * BK * SROW;
        const float* BL = SB + (st * 2 + 1) * BK * SROW;

#pragma unroll
        for (int ks = 0; ks < BK; ks += 8) {
            uint32_t bh[4][2], bl[4][2];
#pragma unroll
            for (int fn = 0; fn < 4; fn++) {
                int n = wn + fn * 8 + g;
                bh[fn][0] = __float_as_uint(BH[(ks + t    ) * SROW + n]);
                bh[fn][1] = __float_as_uint(BH[(ks + t + 4) * SROW + n]);
                bl[fn][0] = __float_as_uint(BL[(ks + t    ) * SROW + n]);
                bl[fn][1] = __float_as_uint(BL[(ks + t + 4) * SROW + n]);
            }
#pragma unroll
            for (int fm = 0; fm < 4; fm++) {
                int m = wm + fm * 16 + g;
                uint32_t ah[4], al[4];
                ah[0] = __float_as_uint(AH[(ks + t    ) * SROW + m]);
                ah[1] = __float_as_uint(AH[(ks + t    ) * SROW + m + 8]);
                ah[2] = __float_as_uint(AH[(ks + t + 4) * SROW + m]);
                ah[3] = __float_as_uint(AH[(ks + t + 4) * SROW + m + 8]);
                al[0] = __float_as_uint(AL[(ks + t    ) * SROW + m]);
                al[1] = __float_as_uint(AL[(ks + t    ) * SROW + m + 8]);
                al[2] = __float_as_uint(AL[(ks + t + 4) * SROW + m]);
                al[3] = __float_as_uint(AL[(ks + t + 4) * SROW + m + 8]);
#pragma unroll
                for (int fn = 0; fn < 4; fn++) {
                    MMA_TF32(acc[fm][fn], al, bh[fn]);   // lo*hi
                    MMA_TF32(acc[fm][fn], ah, bl[fn]);   // hi*lo
                    MMA_TF32(acc[fm][fn], ah, bh[fn]);   // hi*hi
                }
            }
        }

        if (tt + 1 < ntiles) {
            store((tt + 1) & 1);   // other stage: safe vs current compute
            __syncthreads();       // one barrier per tile
        }
    }

    // ---- epilogue ----
#pragma unroll
    for (int fm = 0; fm < 4; fm++) {
        int r0 = bm + wm + fm * 16 + g;
        int r1 = r0 + 8;
#pragma unroll
        for (int fn = 0; fn < 4; fn++) {
            int cn = bn + wn + fn * 8 + 2 * t;
            float v0 = acc[fm][fn][0] * alpha;
            float v1 = acc[fm][fn][1] * alpha;
            float v2 = acc[fm][fn][2] * alpha;
            float v3 = acc[fm][fn][3] * alpha;
            if (bias) { float b0 = bias[cn], b1x = bias[cn + 1];
                        v0 += b0; v1 += b1x; v2 += b0; v3 += b1x; }
            if (Rb)   { v0 += Rb[(long)r0 * ldc + cn];
                        v1 += Rb[(long)r0 * ldc + cn + 1];
                        v2 += Rb[(long)r1 * ldc + cn];
                        v3 += Rb[(long)r1 * ldc + cn + 1]; }
            if (relu) { v0 = fmaxf(v0, 0.f); v1 = fmaxf(v1, 0.f);
                        v2 = fmaxf(v2, 0.f); v3 = fmaxf(v3, 0.f); }
            *(float2*)(Cb + (long)r0 * ldc + cn) = make_float2(v0, v1);
            *(float2*)(Cb + (long)r1 * ldc + cn) = make_float2(v2, v3);
        }
    }
}

static constexpr size_t GEMM_TC_SMEM = (size_t)(2 * 2 * 16 * 136) * 2 * sizeof(float); // 69632

// ===========================================================================
// FFMA GEMM (small xq/xk convs, M=64 per batch)
// ===========================================================================
template<int BM, int BN, int BK, int TM, int TN, bool AKM, bool BKM, int PA, int PB>
__global__ void __launch_bounds__((BM/TM)*(BN/TN))
gemm_k(const float* __restrict__ A, const float* __restrict__ B, float* __restrict__ C,
       int K, int lda, int ldb, int ldc,
       long asb, long bsb, long csb, int aMod, int bMod,
       float alpha, const float* __restrict__ bias,
       const float* __restrict__ res, int relu)
{
    constexpr int NT = (BM/TM)*(BN/TN);
    const int z = blockIdx.z;
    const float* Ab = A + (aMod ? (long)(z % aMod) * asb : (long)z * asb);
    const float* Bb = B + (bMod ? (long)(z % bMod) * bsb : (long)z * bsb);
    float* Cb = C + (long)z * csb;
    const float* Rb = res ? (res + (long)z * csb) : nullptr;

    const int bm = blockIdx.y * BM;
    const int bn = blockIdx.x * BN;

    __shared__ float As[BK][BM + PA];
    __shared__ float Bs[BK][BN + PB];

    const int tid = threadIdx.x;
    const int tx = tid % (BN / TN);
    const int ty = tid / (BN / TN);

    float acc[TM][TN];
#pragma unroll
    for (int i = 0; i < TM; i++)
#pragma unroll
        for (int j = 0; j < TN; j++) acc[i][j] = 0.f;

    for (int kt = 0; kt < K; kt += BK) {
        if (AKM) {
#pragma unroll
            for (int v = tid; v < BK * BM / 4; v += NT) {
                int kk = v / (BM / 4), mv = v % (BM / 4);
                float4 tv = *(const float4*)(Ab + (long)(kt + kk) * lda + bm + mv * 4);
                *(float4*)&As[kk][mv * 4] = tv;
            }
        } else {
#pragma unroll
            for (int v = tid; v < BK * BM / 4; v += NT) {
                int mm = v / (BK / 4), kv = v % (BK / 4);
                float4 tv = *(const float4*)(Ab + (long)(bm + mm) * lda + kt + kv * 4);
                As[kv * 4 + 0][mm] = tv.x;
                As[kv * 4 + 1][mm] = tv.y;
                As[kv * 4 + 2][mm] = tv.z;
                As[kv * 4 + 3][mm] = tv.w;
            }
        }
        if (BKM) {
#pragma unroll
            for (int v = tid; v < BK * BN / 4; v += NT) {
                int kk = v / (BN / 4), nv = v % (BN / 4);
                float4 tv = *(const float4*)(Bb + (long)(kt + kk) * ldb + bn + nv * 4);
                *(float4*)&Bs[kk][nv * 4] = tv;
            }
        } else {
#pragma unroll
            for (int v = tid; v < BK * BN / 4; v += NT) {
                int nn = v / (BK / 4), kv = v % (BK / 4);
                float4 tv = *(const float4*)(Bb + (long)(bn + nn) * ldb + kt + kv * 4);
                Bs[kv * 4 + 0][nn] = tv.x;
                Bs[kv * 4 + 1][nn] = tv.y;
                Bs[kv * 4 + 2][nn] = tv.z;
                Bs[kv * 4 + 3][nn] = tv.w;
            }
        }
        __syncthreads();

#pragma unroll
        for (int kk = 0; kk < BK; kk++) {
            float a[TM], bfr[TN];
            float4 a0 = *(const float4*)&As[kk][ty * TM];
            float4 a1 = *(const float4*)&As[kk][ty * TM + 4];
            a[0]=a0.x; a[1]=a0.y; a[2]=a0.z; a[3]=a0.w;
            a[4]=a1.x; a[5]=a1.y; a[6]=a1.z; a[7]=a1.w;
            float4 b0 = *(const float4*)&Bs[kk][tx * TN];
            float4 b1 = *(const float4*)&Bs[kk][tx * TN + 4];
            bfr[0]=b0.x; bfr[1]=b0.y; bfr[2]=b0.z; bfr[3]=b0.w;
            bfr[4]=b1.x; bfr[5]=b1.y; bfr[6]=b1.z; bfr[7]=b1.w;
#pragma unroll
            for (int i = 0; i < TM; i++)
#pragma unroll
                for (int j = 0; j < TN; j++)
                    acc[i][j] = fmaf(a[i], bfr[j], acc[i][j]);
        }
        __syncthreads();
    }

#pragma unroll
    for (int i = 0; i < TM; i++) {
        int cm = bm + ty * TM + i;
#pragma unroll
        for (int j = 0; j < TN; j++) {
            int cn = bn + tx * TN + j;
            float v = acc[i][j] * alpha;
            if (bias) v += bias[cn];
            if (Rb)   v += Rb[(long)cm * ldc + cn];
            if (relu) v = fmaxf(v, 0.f);
            Cb[(long)cm * ldc + cn] = v;
        }
    }
}

// ===========================================================================
// In-place row softmax over last dim of E[z][n][1024]
// ===========================================================================
__global__ void softmax_inplace_k(float* __restrict__ E)
{
    const int n = blockIdx.x;
    const int z = blockIdx.y;
    float* row = E + ((long)z * NN + n) * NN;
    const int tid = threadIdx.x;  // 256

    float e[4];
#pragma unroll
    for (int k = 0; k < 4; k++) e[k] = row[tid + 256 * k];

    __shared__ float red[256];
    float m = fmaxf(fmaxf(e[0], e[1]), fmaxf(e[2], e[3]));
    red[tid] = m; __syncthreads();
    for (int s = 128; s > 0; s >>= 1) {
        if (tid < s) red[tid] = fmaxf(red[tid], red[tid + s]);
        __syncthreads();
    }
    m = red[0]; __syncthreads();

    float ssum = 0.f;
#pragma unroll
    for (int k = 0; k < 4; k++) { e[k] = expf(e[k] - m); ssum += e[k]; }
    red[tid] = ssum; __syncthreads();
    for (int s = 128; s > 0; s >>= 1) {
        if (tid < s) red[tid] += red[tid + s];
        __syncthreads();
    }
    float inv = 1.f / red[0];
#pragma unroll
    for (int k = 0; k < 4; k++) row[tid + 256 * k] = e[k] * inv;
}

// ===========================================================================
// LN1 (fused 3-way mean of Rt12 + residual): h[t][c] = LN_c(x[b][c][n] + xr)
// ===========================================================================
__global__ void ln1_k(const float* __restrict__ x, const float* __restrict__ Rt12,
                      const float* __restrict__ gam, const float* __restrict__ bet,
                      float* __restrict__ h)
{
    const int t = blockIdx.x;
    const int b = t >> 10, n = t & 1023;
    const int c = threadIdx.x;
    long base = ((long)(3 * b) * NN + n) * CC + c;
    float r = Rt12[base] + Rt12[base + (long)NN * CC] + Rt12[base + 2L * NN * CC];
    float v = x[((long)b * CC + c) * NN + n] + r * (1.f / 48.f);

    __shared__ float red[256];
    red[c] = v; __syncthreads();
    for (int s = 128; s > 0; s >>= 1) { if (c < s) red[c] += red[c + s]; __syncthreads(); }
    float mu = red[0] * (1.f / CC); __syncthreads();
    float d = v - mu;
    red[c] = d * d; __syncthreads();
    for (int s = 128; s > 0; s >>= 1) { if (c < s) red[c] += red[c + s]; __syncthreads(); }
    float var = red[0] * (1.f / CC);
    h[(long)t * CC + c] = d * rsqrtf(var + 1e-6f) * gam[c] + bet[c];
}

// ===========================================================================
// LN2 (fused MLP2 split-K reduce + bias + residual) + relu + transposed write
// ===========================================================================
__global__ void ln2_out_k(const float* __restrict__ P4, const float* __restrict__ h,
                          const float* __restrict__ b2,
                          const float* __restrict__ gam, const float* __restrict__ bet,
                          float* __restrict__ out)
{
    const int t = blockIdx.x;
    const int b = t >> 10, n = t & 1023;
    const int c = threadIdx.x;
    long idx = (long)t * CC + c;
    float v = h[idx] + b2[c];
#pragma unroll
    for (int z = 0; z < 4; z++) v += P4[(long)z * TOK * CC + idx];

    __shared__ float red[256];
    red[c] = v; __syncthreads();
    for (int s = 128; s > 0; s >>= 1) { if (c < s) red[c] += red[c + s]; __syncthreads(); }
    float mu = red[0] * (1.f / CC); __syncthreads();
    float d = v - mu;
    red[c] = d * d; __syncthreads();
    for (int s = 128; s > 0; s >>= 1) { if (c < s) red[c] += red[c + s]; __syncthreads(); }
    float var = red[0] * (1.f / CC);
    float hv = d * rsqrtf(var + 1e-6f) * gam[c] + bet[c];
    out[((long)b * CC + c) * NN + n] = fmaxf(hv, 0.f);
}

// ===========================================================================
extern "C" void kernel_launch(void* const* d_in, const int* in_sizes, int n_in,
                              void* d_out, int out_size)
{
    (void)in_sizes; (void)n_in; (void)out_size;
    const float* x     = (const float*)d_in[0];
    const float* Wq    = (const float*)d_in[1];
    const float* Wk    = (const float*)d_in[2];
    const float* Wv    = (const float*)d_in[3];
    const float* bv    = (const float*)d_in[4];
    const float* ln1_g = (const float*)d_in[5];
    const float* ln1_b = (const float*)d_in[6];
    const float* W1    = (const float*)d_in[7];
    const float* b1    = (const float*)d_in[8];
    const float* W2    = (const float*)d_in[9];
    const float* b2    = (const float*)d_in[10];
    const float* ln2_g = (const float*)d_in[11];
    const float* ln2_b = (const float*)d_in[12];
    float* out = (float*)d_out;

    // raise dynamic smem cap for the TC kernels (host-side config; idempotent)
    cudaFuncSetAttribute(gemm_tc<true,true>,   cudaFuncAttributeMaxDynamicSharedMemorySize, (int)GEMM_TC_SMEM);
    cudaFuncSetAttribute(gemm_tc<true,false>,  cudaFuncAttributeMaxDynamicSharedMemorySize, (int)GEMM_TC_SMEM);
    cudaFuncSetAttribute(gemm_tc<false,false>, cudaFuncAttributeMaxDynamicSharedMemorySize, (int)GEMM_TC_SMEM);

    float* S = nullptr;
    cudaGetSymbolAddress((void**)&S, g_scratch);
    float* xq   = S + OFF_XQ;
    float* xk   = S + OFF_XK;
    float* xvT  = S + OFF_XVT;
    float* E    = S + OFF_E;
    float* Rt12 = S + OFF_RT12;
    float* h    = S + OFF_H;
    float* H1   = S + OFF_H1;
    float* P4   = S + OFF_P4;

    const float* xlast = x + (long)NB * CC * NN;

    // out[4:] = last (unchanged)
    cudaMemcpyAsync(out + (long)NB * CC * NN, xlast,
                    (size_t)12 * CC * NN * sizeof(float),
                    cudaMemcpyDeviceToDevice, 0);

    // xq[z=(B,s)][o][n] = Wq[s] @ last[B, s*64.., :]  (48 batches 64x1024x64, FFMA)
    gemm_k<64,128,16,8,8,false,true,4,0><<<dim3(8,1,48),128>>>(
        Wq, xlast, xq, 64, 64, NN, NN,
        (long)64*64, (long)64*NN, (long)64*NN, 4, 0,
        1.f, nullptr, nullptr, 0);

    // xk: 16 batches 64x1024x64 over first (FFMA)
    gemm_k<64,128,16,8,8,false,true,4,0><<<dim3(8,1,16),128>>>(
        Wk, x, xk, 64, 64, NN, NN,
        (long)64*64, (long)64*NN, (long)64*NN, 4, 0,
        1.f, nullptr, nullptr, 0);

    // xvT[b][n][c] = (Wv @ x[b])^T + bv   (4 batches 1024x256x256, TC)
    gemm_tc<true,false><<<dim3(2,8,4),256,GEMM_TC_SMEM>>>(
        x, Wv, xvT, CC, NN, CC, CC,
        (long)CC*NN, 0L, (long)NN*CC, 0, 0,
        1.f, bv, nullptr, 0);

    // energy: E[z][n][m] = sum_ch xq[z][ch][n] * xk[z%4][ch][m]  (12 x 1024x1024x256, TC)
    gemm_tc<true,true><<<dim3(8,8,12),256,GEMM_TC_SMEM>>>(
        xq, xk, E, CC, NN, NN, NN,
        (long)CC*NN, (long)CC*NN, (long)NN*NN, 0, 4,
        1.f, nullptr, nullptr, 0);

    // softmax rows in place
    softmax_inplace_k<<<dim3(NN, NZ), 256>>>(E);

    // per-z apply: Rt12[z][m][c] = sum_k attn[z][k][m] * xvT[z%4][k][c]  (12 x 1024x256x1024, TC)
    gemm_tc<true,true><<<dim3(2,8,12),256,GEMM_TC_SMEM>>>(
        E, xvT, Rt12, NN, NN, CC, CC,
        (long)NN*NN, (long)NN*CC, (long)NN*CC, 0, 4,
        1.f, nullptr, nullptr, 0);

    // LN1 (3-way mean * 1/48 + residual fused)
    ln1_k<<<TOK, 256>>>(x, Rt12, ln1_g, ln1_b, h);

    // MLP1: H1 = relu(h @ W1^T + b1)   (4096x1024x256, TC)
    gemm_tc<false,false><<<dim3(8,32,1),256,GEMM_TC_SMEM>>>(
        h, W1, H1, CC, CC, CC, 4*CC,
        0L, 0L, 0L, 0, 0,
        1.f, b1, nullptr, 1);

    // MLP2 split-K (4 chunks of K=256): P4[z] = H1[:, z*256:+256] @ W2[:, z*256:+256]^T
    gemm_tc<false,false><<<dim3(2,32,4),256,GEMM_TC_SMEM>>>(
        H1, W2, P4, CC, 4*CC, 4*CC, CC,
        256L, 256L, (long)TOK*CC, 0, 0,
        1.f, nullptr, nullptr, 0);

    // LN2 (split-K reduce + b2 + residual h fused) + relu + transpose into out[:4]
    ln2_out_k<<<TOK, 256>>>(P4, h, b2, ln2_g, ln2_b, out);
}